// round 6
// baseline (speedup 1.0000x reference)
#include <cuda_runtime.h>
#include <cuda.h>
#include <cuda_fp16.h>
#include <cstdint>

// ---------------------------------------------------------------------------
// Arch feature detection: tcgen05 requires an sm_10xa target. The harness's
// device pass may be plain compute_103, where only baseline PTX is legal.
// ---------------------------------------------------------------------------
#if defined(__CUDA_ARCH__)
#ifdef __CUDA_ARCH_HAS_FEATURE__
#if __CUDA_ARCH_HAS_FEATURE__(SM103_ALL)
#define HAS_TCGEN05 1
#endif
#endif
#endif

// ---------------------------------------------------------------------------
// Problem constants
// ---------------------------------------------------------------------------
#define T_DIM 8192
#define DIN   4096
#define DOUT  4096

#define BM 128
#define BN 256

// ------------------------- tcgen05 path constants --------------------------
#define BK 64                    // fp16 elems -> 128 bytes per row (SW128 atom)
#define STAGES 4
#define NCHUNK (DIN / BK)        // 64
#define KSTEPS_PER_CHUNK 4       // BK / 16

#define STAGE_A_BYTES (BM * BK * 2)   // 16384
#define STAGE_B_BYTES (BN * BK * 2)   // 32768
#define STAGE_BYTES   (STAGE_A_BYTES + STAGE_B_BYTES)  // 49152

#define SMEM_TMEM_PTR 0
#define SMEM_FULL(s)  (16 + 8 * (s))
#define SMEM_EMPTY(s) (64 + 8 * (s))
#define SMEM_BIAS     128
#define SMEM_STAGE(s) (2048 + (s) * STAGE_BYTES)
#define SMEM_A(s)     SMEM_STAGE(s)
#define SMEM_B(s)     (SMEM_STAGE(s) + STAGE_A_BYTES)
#define SMEM_TOTAL    (2048 + STAGES * STAGE_BYTES)   // 198656 bytes

#define TMEM_COLS 256

// idesc for kind::f16 (fp16 in, fp32 accum): dtype=F32 bit4, atype/btype=F16(0),
// N>>3 at [17:22], M>>4 at [24:28]
#define MMA_IDESC ((1u << 4) | ((BN / 8) << 17) | ((BM / 16) << 24))

// ------------------------- fallback (mma.sync) constants -------------------
#define FB_BK 32
#define FB_STAGES 4
#define FB_NCHUNK (DIN / FB_BK)          // 128
#define FB_ROWH 40                        // padded halfs per smem row (+16B)
#define FB_A_BYTES (BM * FB_ROWH * 2)     // 10240
#define FB_B_BYTES (BN * FB_ROWH * 2)     // 20480
#define FB_STAGE_BYTES (FB_A_BYTES + FB_B_BYTES)  // 30720

// ---------------------------------------------------------------------------
// Common helpers
// ---------------------------------------------------------------------------
__device__ __forceinline__ uint32_t smem_to_u32(const void* smem_ptr) {
    uint32_t addr;
    asm("{ .reg .u64 tmp; cvta.to.shared.u64 tmp, %1; cvt.u32.u64 %0, tmp; }"
        : "=r"(addr) : "l"(smem_ptr));
    return addr;
}

// ---------------------------------------------------------------------------
// tcgen05-path helpers (PTX only emitted when HAS_TCGEN05)
// ---------------------------------------------------------------------------
#if defined(HAS_TCGEN05)
__device__ __forceinline__ uint32_t elect_one_pred() {
    uint32_t pred;
    asm volatile(
        "{\n\t"
        ".reg .pred p;\n\t"
        "elect.sync _|p, 0xFFFFFFFF;\n\t"
        "selp.b32 %0, 1, 0, p;\n\t"
        "}"
        : "=r"(pred));
    return pred;
}

#define MBARRIER_INIT(mbar, count) \
    asm volatile("mbarrier.init.shared.b64 [%0], %1;" \
        :: "r"((uint32_t)(mbar)), "r"((uint32_t)(count)) : "memory")

#define MBARRIER_EXPECT_TX(mbar, tx) \
    asm volatile("mbarrier.arrive.expect_tx.shared.b64 _, [%0], %1;" \
        :: "r"((uint32_t)(mbar)), "r"((uint32_t)(tx)) : "memory")

#define MBARRIER_WAIT_PARITY(mbar, parity) do { \
    uint32_t _mbar = (uint32_t)(mbar); \
    uint32_t _parity = (uint32_t)(parity); \
    uint32_t _done; \
    asm volatile( \
        "{\n\t" \
        ".reg .pred p;\n\t" \
        "mbarrier.try_wait.parity.acquire.cta.shared::cta.b64 p, [%1], %2;\n\t" \
        "selp.b32 %0, 1, 0, p;\n\t" \
        "}" \
        : "=r"(_done) : "r"(_mbar), "r"(_parity) : "memory"); \
    if (!_done) { \
        asm volatile( \
            "{\n\t" \
            ".reg .pred P1;\n\t" \
            "WAIT_LOOP_%=:\n\t" \
            "mbarrier.try_wait.parity.acquire.cta.shared::cta.b64 P1, [%0], %1, 0x989680;\n\t" \
            "@P1 bra.uni WAIT_DONE_%=;\n\t" \
            "bra.uni WAIT_LOOP_%=;\n\t" \
            "WAIT_DONE_%=:\n\t" \
            "}" \
            :: "r"(_mbar), "r"(_parity) : "memory"); \
    } \
} while(0)

#define MBARRIER_INVAL(mbar) \
    asm volatile("mbarrier.inval.shared.b64 [%0];" :: "r"((uint32_t)(mbar)) : "memory")

#define TCGEN05_ALLOC(sp, nCols) \
    asm volatile("tcgen05.alloc.cta_group::1.sync.aligned.shared::cta.b32 [%0], %1;" \
        :: "r"((uint32_t)(sp)), "r"((uint32_t)(nCols)) : "memory")
#define TCGEN05_DEALLOC(tm, nCols) \
    asm volatile("tcgen05.dealloc.cta_group::1.sync.aligned.b32 %0, %1;" \
        :: "r"(tm), "r"((uint32_t)(nCols)))
#define TCGEN05_RELINQUISH_ALLOC_PERMIT() \
    asm volatile("tcgen05.relinquish_alloc_permit.cta_group::1.sync.aligned;")
#define TCGEN05_COMMIT(mbar) \
    asm volatile("tcgen05.commit.cta_group::1.mbarrier::arrive::one.shared::cluster.b64 [%0];" \
        :: "r"((uint32_t)(mbar)) : "memory")
#define TCGEN05_FENCE_BEFORE() \
    asm volatile("tcgen05.fence::before_thread_sync;" ::: "memory")
#define TCGEN05_FENCE_AFTER() \
    asm volatile("tcgen05.fence::after_thread_sync;" ::: "memory")
#define TCGEN05_WAIT_LD() \
    asm volatile("tcgen05.wait::ld.sync.aligned;" ::: "memory")

#define TCGEN05_LD_32X32B_X32(r, tmem_addr) \
    asm volatile( \
        "tcgen05.ld.sync.aligned.32x32b.x32.b32 " \
        "{%0, %1, %2, %3, %4, %5, %6, %7, " \
        " %8, %9, %10, %11, %12, %13, %14, %15, " \
        " %16, %17, %18, %19, %20, %21, %22, %23, " \
        " %24, %25, %26, %27, %28, %29, %30, %31}, [%32];" \
        : "=r"((r)[0]),  "=r"((r)[1]),  "=r"((r)[2]),  "=r"((r)[3]), \
          "=r"((r)[4]),  "=r"((r)[5]),  "=r"((r)[6]),  "=r"((r)[7]), \
          "=r"((r)[8]),  "=r"((r)[9]),  "=r"((r)[10]), "=r"((r)[11]), \
          "=r"((r)[12]), "=r"((r)[13]), "=r"((r)[14]), "=r"((r)[15]), \
          "=r"((r)[16]), "=r"((r)[17]), "=r"((r)[18]), "=r"((r)[19]), \
          "=r"((r)[20]), "=r"((r)[21]), "=r"((r)[22]), "=r"((r)[23]), \
          "=r"((r)[24]), "=r"((r)[25]), "=r"((r)[26]), "=r"((r)[27]), \
          "=r"((r)[28]), "=r"((r)[29]), "=r"((r)[30]), "=r"((r)[31]) \
        : "r"(tmem_addr))

static constexpr uint64_t SMEM_DESC_BASE_SW128 =
    (uint64_t(2)  << 61) | (uint64_t(1) << 46) | (uint64_t(64) << 32) | (uint64_t(1) << 16);
#define MAKE_SMEM_DESC(base_addr) \
    (SMEM_DESC_BASE_SW128 | ((uint64_t)((base_addr) >> 4) & 0x3FFF))

#define TMA_LOAD_2D(sa, tmap, cx, cy, mbar) \
    asm volatile( \
        "cp.async.bulk.tensor.2d.shared::cta.global.tile.mbarrier::complete_tx::bytes " \
        "[%0], [%1, {%2, %3}], [%4];" \
        :: "r"((uint32_t)(sa)), "l"(tmap), \
           "r"((int32_t)(cx)), "r"((int32_t)(cy)), "r"((uint32_t)(mbar)) \
        : "memory")

__device__ __forceinline__ void mma_f16_ss(uint32_t d_tmem, uint64_t a_desc,
                                           uint64_t b_desc, uint32_t idesc,
                                           uint32_t accumulate) {
    asm volatile(
        "{\n\t"
        ".reg .pred p;\n\t"
        "setp.ne.u32 p, %5, 0;\n\t"
        "tcgen05.mma.cta_group::1.kind::f16 [%0], %1, %2, %3, {%4, %4, %4, %4}, p;\n\t"
        "}"
        :: "r"(d_tmem), "l"(a_desc), "l"(b_desc), "r"(idesc),
           "r"(0u), "r"(accumulate)
        : "memory");
}
#endif  // HAS_TCGEN05

// ---------------------------------------------------------------------------
// Fallback helpers (baseline PTX: sm_80-era, legal on compute_103)
// ---------------------------------------------------------------------------
#define CP_ASYNC16(sm, gp) \
    asm volatile("cp.async.cg.shared.global [%0], [%1], 16;" \
        :: "r"((uint32_t)(sm)), "l"(gp) : "memory")
#define CP_COMMIT() asm volatile("cp.async.commit_group;" ::: "memory")
#define CP_WAIT2()  asm volatile("cp.async.wait_group 2;" ::: "memory")

#define LDSM_X4(r, addr) \
    asm volatile("ldmatrix.sync.aligned.m8n8.x4.shared.b16 {%0,%1,%2,%3}, [%4];" \
        : "=r"((r)[0]), "=r"((r)[1]), "=r"((r)[2]), "=r"((r)[3]) : "r"(addr))

#define MMA16816(d, a, b0_, b1_) \
    asm volatile( \
        "mma.sync.aligned.m16n8k16.row.col.f32.f16.f16.f32 " \
        "{%0,%1,%2,%3}, {%4,%5,%6,%7}, {%8,%9}, {%0,%1,%2,%3};" \
        : "+f"((d)[0]), "+f"((d)[1]), "+f"((d)[2]), "+f"((d)[3]) \
        : "r"((a)[0]), "r"((a)[1]), "r"((a)[2]), "r"((a)[3]), "r"(b0_), "r"(b1_))

// ---------------------------------------------------------------------------
// Device-global fp16 scratch (allocation-free)
// ---------------------------------------------------------------------------
__device__ __align__(1024) __half g_x_h[(size_t)T_DIM * DIN];  // 64 MB
__device__ __align__(1024) __half g_w_h[(size_t)DOUT * DIN];   // 32 MB

// ---------------------------------------------------------------------------
// fp32 -> fp16 conversion
// ---------------------------------------------------------------------------
__global__ void __launch_bounds__(256) cvt_f32_to_f16_kernel(
    const float* __restrict__ in, __half* __restrict__ out, int n8)
{
    int i = blockIdx.x * blockDim.x + threadIdx.x;
    if (i >= n8) return;
    const float4* p = reinterpret_cast<const float4*>(in) + (size_t)i * 2;
    float4 a = p[0];
    float4 b = p[1];
    __half2 h0 = __floats2half2_rn(a.x, a.y);
    __half2 h1 = __floats2half2_rn(a.z, a.w);
    __half2 h2 = __floats2half2_rn(b.x, b.y);
    __half2 h3 = __floats2half2_rn(b.z, b.w);
    uint4 v;
    v.x = *reinterpret_cast<uint32_t*>(&h0);
    v.y = *reinterpret_cast<uint32_t*>(&h1);
    v.z = *reinterpret_cast<uint32_t*>(&h2);
    v.w = *reinterpret_cast<uint32_t*>(&h3);
    reinterpret_cast<uint4*>(out)[i] = v;
}

// ---------------------------------------------------------------------------
// GEMM kernel: C[T, DOUT] = Xh * Wh^T + b.  One CTA = 128 x 256 tile,
// 256 threads. tcgen05 path when the target supports it; otherwise a
// cp.async + ldmatrix + mma.sync fp16 pipeline (TN layout, no .trans).
// ---------------------------------------------------------------------------
__global__ void __launch_bounds__(256, 1) temporal_linear_gemm_kernel(
    const __grid_constant__ CUtensorMap tma_a,
    const __grid_constant__ CUtensorMap tma_b,
    const __half* __restrict__ xh,
    const __half* __restrict__ wh,
    const float* __restrict__ bias,
    float* __restrict__ out)
{
    extern __shared__ char smem[];
    uint32_t smem_base = smem_to_u32(smem);
    const int tid = threadIdx.x;
    const int wid = tid >> 5;
    const int lid = tid & 31;
    const int m_base = blockIdx.y * BM;
    const int n_base = blockIdx.x * BN;

#if defined(HAS_TCGEN05)
    // =======================================================================
    // tcgen05 path
    // =======================================================================
    {
        float* bs = reinterpret_cast<float*>(smem + SMEM_BIAS);
        bs[tid] = bias[n_base + tid];
    }

    if (wid == 0) {
        TCGEN05_ALLOC(smem_base + SMEM_TMEM_PTR, TMEM_COLS);
    }
    if (tid == 0) {
        #pragma unroll
        for (int s = 0; s < STAGES; s++) {
            MBARRIER_INIT(smem_base + SMEM_FULL(s), 1);
            MBARRIER_INIT(smem_base + SMEM_EMPTY(s), 1);
        }
    }
    __syncthreads();

    uint32_t tmem_base;
    asm volatile("ld.shared.b32 %0, [%1];"
                 : "=r"(tmem_base) : "r"(smem_base + SMEM_TMEM_PTR));

    if (wid == 0 && elect_one_pred()) {
        #pragma unroll
        for (int s = 0; s < STAGES; s++) {
            MBARRIER_EXPECT_TX(smem_base + SMEM_FULL(s), STAGE_BYTES);
            TMA_LOAD_2D(smem_base + SMEM_A(s), &tma_a, s * BK, m_base,
                        smem_base + SMEM_FULL(s));
            TMA_LOAD_2D(smem_base + SMEM_B(s), &tma_b, s * BK, n_base,
                        smem_base + SMEM_FULL(s));
        }

        for (int i = 0; i < NCHUNK; i++) {
            int s = i & (STAGES - 1);
            int r = i >> 2;
            MBARRIER_WAIT_PARITY(smem_base + SMEM_FULL(s), r & 1);

            uint64_t adesc = MAKE_SMEM_DESC(smem_base + SMEM_A(s));
            uint64_t bdesc = MAKE_SMEM_DESC(smem_base + SMEM_B(s));
            #pragma unroll
            for (int k = 0; k < KSTEPS_PER_CHUNK; k++) {
                mma_f16_ss(tmem_base, adesc + k * 2, bdesc + k * 2,
                           MMA_IDESC, (i > 0 || k > 0) ? 1u : 0u);
            }
            TCGEN05_COMMIT(smem_base + SMEM_EMPTY(s));

            int j = i - 1;
            if (j >= 0 && j + STAGES < NCHUNK) {
                int sp = j & (STAGES - 1);
                int rp = j >> 2;
                MBARRIER_WAIT_PARITY(smem_base + SMEM_EMPTY(sp), rp & 1);
                MBARRIER_EXPECT_TX(smem_base + SMEM_FULL(sp), STAGE_BYTES);
                TMA_LOAD_2D(smem_base + SMEM_A(sp), &tma_a, (j + STAGES) * BK,
                            m_base, smem_base + SMEM_FULL(sp));
                TMA_LOAD_2D(smem_base + SMEM_B(sp), &tma_b, (j + STAGES) * BK,
                            n_base, smem_base + SMEM_FULL(sp));
            }
        }
        {
            int last = NCHUNK - 1;
            MBARRIER_WAIT_PARITY(smem_base + SMEM_EMPTY(last & (STAGES - 1)),
                                 (last >> 2) & 1);
        }
    }

    __syncthreads();
    TCGEN05_FENCE_AFTER();

    // Epilogue: 8 warps; warps 0-3 cols [0,128), warps 4-7 cols [128,256).
    {
        const float* bs = reinterpret_cast<const float*>(smem + SMEM_BIAS);
        int colgrp = (wid >> 2) * 128;
        int row = m_base + (wid & 3) * 32 + lid;
        float* orow = out + (size_t)row * DOUT + n_base;

        #pragma unroll
        for (int j = 0; j < 4; j++) {
            int c0 = colgrp + j * 32;
            uint32_t r[32];
            TCGEN05_LD_32X32B_X32(r, tmem_base + c0);
            TCGEN05_WAIT_LD();
            #pragma unroll
            for (int c = 0; c < 32; c += 4) {
                float4 v;
                v.x = __uint_as_float(r[c + 0]) + bs[c0 + c + 0];
                v.y = __uint_as_float(r[c + 1]) + bs[c0 + c + 1];
                v.z = __uint_as_float(r[c + 2]) + bs[c0 + c + 2];
                v.w = __uint_as_float(r[c + 3]) + bs[c0 + c + 3];
                *reinterpret_cast<float4*>(orow + c0 + c) = v;
            }
        }
    }

    TCGEN05_FENCE_BEFORE();
    __syncthreads();
    if (tid == 0) {
        #pragma unroll
        for (int s = 0; s < STAGES; s++) {
            MBARRIER_INVAL(smem_base + SMEM_FULL(s));
            MBARRIER_INVAL(smem_base + SMEM_EMPTY(s));
        }
    }
    __syncthreads();
    if (wid == 0) {
        TCGEN05_RELINQUISH_ALLOC_PERMIT();
        TCGEN05_DEALLOC(tmem_base, TMEM_COLS);
    }

#else
    // =======================================================================
    // Fallback: mma.sync fp16 pipeline (baseline PTX)
    // Warp grid 2(m) x 4(n); warp tile 64x64; BK=32; 4-stage cp.async.
    // =======================================================================
    const int wm = wid & 1;
    const int wn = wid >> 1;

    float acc[4][8][4];
    #pragma unroll
    for (int a = 0; a < 4; a++)
        #pragma unroll
        for (int b2 = 0; b2 < 8; b2++)
            #pragma unroll
            for (int c = 0; c < 4; c++)
                acc[a][b2][c] = 0.0f;

    // Per-thread ldmatrix source offsets (TN: both operands k-contiguous,
    // no .trans anywhere).
    // A x4: lane l -> row (l&15), col halfs (l>>4)*8  => frags {a0,a1,a2,a3}
    const uint32_t a_off0 =
        ((uint32_t)(wm * 64 + (lid & 15)) * FB_ROWH + (uint32_t)((lid >> 4) * 8)) * 2;
    // B x4: lane l -> n (l&7) + (l>=16 ? 8 : 0), k offset (l&8)
    const uint32_t b_off0 =
        ((uint32_t)(wn * 64 + (lid & 7) + ((lid & 16) >> 1)) * FB_ROWH +
         (uint32_t)(lid & 8)) * 2;

    auto issue_stage = [&](int s, int kchunk) {
        const int k0 = kchunk * FB_BK;
        const uint32_t sa = smem_base + (uint32_t)s * FB_STAGE_BYTES;
        const uint32_t sb = sa + FB_A_BYTES;
        #pragma unroll
        for (int i = 0; i < 2; i++) {          // A: 512 16B chunks / 256 thr
            int c = tid + 256 * i;
            int row = c >> 2, kc = c & 3;
            uint32_t dst = sa + ((uint32_t)row * FB_ROWH + kc * 8) * 2;
            const __half* src = xh + (size_t)(m_base + row) * DIN + k0 + kc * 8;
            CP_ASYNC16(dst, src);
        }
        #pragma unroll
        for (int i = 0; i < 4; i++) {          // B: 1024 16B chunks / 256 thr
            int c = tid + 256 * i;
            int row = c >> 2, kc = c & 3;
            uint32_t dst = sb + ((uint32_t)row * FB_ROWH + kc * 8) * 2;
            const __half* src = wh + (size_t)(n_base + row) * DIN + k0 + kc * 8;
            CP_ASYNC16(dst, src);
        }
    };

    // Prologue: stages 0..2
    for (int s = 0; s < FB_STAGES - 1; s++) {
        issue_stage(s, s);
        CP_COMMIT();
    }

    for (int i = 0; i < FB_NCHUNK; i++) {
        CP_WAIT2();              // stage i's group complete
        __syncthreads();

        if (i + FB_STAGES - 1 < FB_NCHUNK)
            issue_stage((i + FB_STAGES - 1) & (FB_STAGES - 1), i + FB_STAGES - 1);
        CP_COMMIT();             // commit (possibly empty) to keep counts aligned

        const int s = i & (FB_STAGES - 1);
        const uint32_t sa = smem_base + (uint32_t)s * FB_STAGE_BYTES;
        const uint32_t sb = sa + FB_A_BYTES;

        #pragma unroll
        for (int kk = 0; kk < 2; kk++) {       // two k16 steps per BK=32
            uint32_t af[4][4], bf[4][4];
            #pragma unroll
            for (int mt = 0; mt < 4; mt++)
                LDSM_X4(af[mt], sa + a_off0 + (uint32_t)(mt * 16) * FB_ROWH * 2 + kk * 32);
            #pragma unroll
            for (int nt = 0; nt < 4; nt++)
                LDSM_X4(bf[nt], sb + b_off0 + (uint32_t)(nt * 16) * FB_ROWH * 2 + kk * 32);
            #pragma unroll
            for (int mt = 0; mt < 4; mt++) {
                #pragma unroll
                for (int nt = 0; nt < 4; nt++) {
                    MMA16816(acc[mt][2 * nt + 0], af[mt], bf[nt][0], bf[nt][1]);
                    MMA16816(acc[mt][2 * nt + 1], af[mt], bf[nt][2], bf[nt][3]);
                }
            }
        }
        __syncthreads();
    }

    // Epilogue: d-frag (row = lane/4 (+8), cols (lane%4)*2 +{0,1}) + bias
    #pragma unroll
    for (int mt = 0; mt < 4; mt++) {
        int row0 = m_base + wm * 64 + mt * 16 + (lid >> 2);
        #pragma unroll
        for (int nt8 = 0; nt8 < 8; nt8++) {
            int col = n_base + wn * 64 + nt8 * 8 + (lid & 3) * 2;
            float b0 = __ldg(bias + col);
            float b1 = __ldg(bias + col + 1);
            float2 v0 = make_float2(acc[mt][nt8][0] + b0, acc[mt][nt8][1] + b1);
            float2 v1 = make_float2(acc[mt][nt8][2] + b0, acc[mt][nt8][3] + b1);
            *reinterpret_cast<float2*>(out + (size_t)row0 * DOUT + col) = v0;
            *reinterpret_cast<float2*>(out + (size_t)(row0 + 8) * DOUT + col) = v1;
        }
    }
#endif
}

// ---------------------------------------------------------------------------
// Host launch
// ---------------------------------------------------------------------------
typedef CUresult (*PFN_cuTensorMapEncodeTiled_v12000)(
    CUtensorMap*, CUtensorMapDataType, cuuint32_t, void*,
    const cuuint64_t*, const cuuint64_t*, const cuuint32_t*, const cuuint32_t*,
    CUtensorMapInterleave, CUtensorMapSwizzle, CUtensorMapL2promotion,
    CUtensorMapFloatOOBfill);

extern "C" void kernel_launch(void* const* d_in, const int* in_sizes, int n_in,
                              void* d_out, int out_size)
{
    const float* x = (const float*)d_in[0];
    const float* W = (const float*)d_in[1];
    const float* b = (const float*)d_in[2];
    float* out = (float*)d_out;

    __half* xh = nullptr;
    __half* wh = nullptr;
    cudaGetSymbolAddress((void**)&xh, g_x_h);
    cudaGetSymbolAddress((void**)&wh, g_w_h);

    {
        int n8x = (T_DIM * DIN) / 8;
        int n8w = (DOUT * DIN) / 8;
        cvt_f32_to_f16_kernel<<<(n8x + 255) / 256, 256>>>(x, xh, n8x);
        cvt_f32_to_f16_kernel<<<(n8w + 255) / 256, 256>>>(W, wh, n8w);
    }

    // TMA descriptors (only consumed by the tcgen05 path; harmless otherwise)
    PFN_cuTensorMapEncodeTiled_v12000 encode = nullptr;
    cudaDriverEntryPointQueryResult qres;
    cudaGetDriverEntryPointByVersion("cuTensorMapEncodeTiled", (void**)&encode,
                                     12000, cudaEnableDefault, &qres);

    CUtensorMap map_a = {}, map_b = {};
    if (encode) {
        {
            cuuint64_t dims[2]    = {(cuuint64_t)DIN, (cuuint64_t)T_DIM};
            cuuint64_t strides[1] = {(cuuint64_t)DIN * sizeof(__half)};
            cuuint32_t box[2]     = {(cuuint32_t)BK, (cuuint32_t)BM};
            cuuint32_t es[2]      = {1, 1};
            encode(&map_a, CU_TENSOR_MAP_DATA_TYPE_FLOAT16, 2, (void*)xh,
                   dims, strides, box, es,
                   CU_TENSOR_MAP_INTERLEAVE_NONE, CU_TENSOR_MAP_SWIZZLE_128B,
                   CU_TENSOR_MAP_L2_PROMOTION_L2_128B,
                   CU_TENSOR_MAP_FLOAT_OOB_FILL_NONE);
        }
        {
            cuuint64_t dims[2]    = {(cuuint64_t)DIN, (cuuint64_t)DOUT};
            cuuint64_t strides[1] = {(cuuint64_t)DIN * sizeof(__half)};
            cuuint32_t box[2]     = {(cuuint32_t)BK, (cuuint32_t)BN};
            cuuint32_t es[2]      = {1, 1};
            encode(&map_b, CU_TENSOR_MAP_DATA_TYPE_FLOAT16, 2, (void*)wh,
                   dims, strides, box, es,
                   CU_TENSOR_MAP_INTERLEAVE_NONE, CU_TENSOR_MAP_SWIZZLE_128B,
                   CU_TENSOR_MAP_L2_PROMOTION_L2_128B,
                   CU_TENSOR_MAP_FLOAT_OOB_FILL_NONE);
        }
    }

    cudaFuncSetAttribute(temporal_linear_gemm_kernel,
                         cudaFuncAttributeMaxDynamicSharedMemorySize, SMEM_TOTAL);

    dim3 grid(DOUT / BN, T_DIM / BM);  // (16, 64)
    temporal_linear_gemm_kernel<<<grid, 256, SMEM_TOTAL>>>(
        map_a, map_b, xh, wh, b, out);
}